// round 14
// baseline (speedup 1.0000x reference)
#include <cuda_runtime.h>
#include <cuda_fp16.h>
#include <math.h>
#include <stdint.h>

#define NN 50000
#define HH 128
#define TT 4
#define EE 150000
#define NE (TT*EE)
#define G3H 384
#define TPAD 136   // halves per smem tile row

// ---------------- scratch (device globals; no allocation allowed) ----------
__device__ __half   g_M16[(size_t)TT*NN*HH];
__device__ __half   g_gx16[(size_t)NN*G3H];
__device__ __half   g_gh16[(size_t)NN*G3H];
__device__ __half   g_gxx16[(size_t)NN*G3H];   // x @ W1ihA^T + bih (constant)
__device__ float    g_h[(size_t)NN*HH];
__device__ __half   g_h16[(size_t)NN*HH];
__device__ __half   g_x16[(size_t)NN*HH];
__device__ __half   g_w16[376832];
__device__ int      g_cnt[NN];
__device__ int      g_off[NN+1];
__device__ int      g_pos[NN];
__device__ unsigned g_ent[NE];

#define OFF_MSGW  0
#define OFF_W0IH  131072
#define OFF_W0HH  180224
#define OFF_W1IH  229376
#define OFF_W1HH  327680

__device__ __forceinline__ uint32_t smem_u32(const void* p) {
    uint32_t a;
    asm("{ .reg .u64 t; cvta.to.shared.u64 t, %1; cvt.u32.u64 %0, t; }" : "=r"(a) : "l"(p));
    return a;
}

#define LDSM_X4(r0, r1, r2, r3, addr) \
    asm volatile("ldmatrix.sync.aligned.m8n8.x4.shared.b16 {%0,%1,%2,%3}, [%4];" \
        : "=r"(r0), "=r"(r1), "=r"(r2), "=r"(r3) : "r"(addr))

// ---------------- fused prologue convert ----------------
__global__ void conv_kernel(const float* __restrict__ x,
                            const float* __restrict__ msgW,
                            const float* __restrict__ w0ih, const float* __restrict__ w0hh,
                            const float* __restrict__ w1ih, const float* __restrict__ w1hh)
{
    int i = blockIdx.x * blockDim.x + threadIdx.x;
    if (i < NN*HH) {
        float v = x[i];
        g_h[i] = v;
        __half hv = __float2half_rn(v);
        g_h16[i] = hv;
        g_x16[i] = hv;
    } else {
        int j = i - NN*HH;
        if (j < 131072)       g_w16[OFF_MSGW + j]            = __float2half_rn(msgW[j]);
        else if (j < 180224)  g_w16[OFF_W0IH + (j - 131072)] = __float2half_rn(w0ih[j - 131072]);
        else if (j < 229376)  g_w16[OFF_W0HH + (j - 180224)] = __float2half_rn(w0hh[j - 180224]);
        else if (j < 327680)  g_w16[OFF_W1IH + (j - 229376)] = __float2half_rn(w1ih[j - 229376]);
        else if (j < 376832)  g_w16[OFF_W1HH + (j - 327680)] = __float2half_rn(w1hh[j - 327680]);
    }
}

// ---------------- CSR build ----------------
__global__ void hist_kernel(const int* __restrict__ edges) {
    int i = blockIdx.x * blockDim.x + threadIdx.x;
    if (i < NE) atomicAdd(&g_cnt[edges[2*i+1]], 1);
}

__global__ void scan_kernel() {
    __shared__ int s[1024];
    __shared__ int carry;
    if (threadIdx.x == 0) carry = 0;
    __syncthreads();
    for (int base = 0; base < NN; base += 1024) {
        int i = base + threadIdx.x;
        int v = (i < NN) ? g_cnt[i] : 0;
        s[threadIdx.x] = v;
        __syncthreads();
        #pragma unroll
        for (int off = 1; off < 1024; off <<= 1) {
            int t = (threadIdx.x >= off) ? s[threadIdx.x - off] : 0;
            __syncthreads();
            s[threadIdx.x] += t;
            __syncthreads();
        }
        int excl = carry + s[threadIdx.x] - v;
        if (i < NN) { g_off[i] = excl; g_pos[i] = excl; }
        __syncthreads();
        if (threadIdx.x == 1023) carry += s[1023];
        __syncthreads();
    }
    if (threadIdx.x == 0) g_off[NN] = carry;
}

__global__ void fill_kernel(const int* __restrict__ edges) {
    int i = blockIdx.x * blockDim.x + threadIdx.x;
    if (i < NE) {
        int t   = i / EE;
        int src = edges[2*i];
        int tgt = edges[2*i+1];
        int p = atomicAdd(&g_pos[tgt], 1);
        g_ent[p] = ((unsigned)t << 16) | (unsigned)src;
    }
}

// ======== shared GEMM pieces ========
__device__ __forceinline__ void stage_half(const __half* __restrict__ A, int row_base,
                                           int row_limit, uint32_t sdst, int h, int tid,
                                           int ld) {
    #pragma unroll
    for (int it = 0; it < 4; it++) {
        int idx = tid + it * 256;
        int r = idx >> 3, c8 = (idx & 7) + h * 8;
        int gr = row_base + r;
        const __half* src = A + (size_t)(gr < row_limit ? gr : 0) * ld + c8 * 8;
        uint32_t dst = sdst + (r * TPAD + c8 * 8) * 2;
        int sz = (gr < row_limit) ? 16 : 0;
        asm volatile("cp.async.cg.shared.global [%0], [%1], 16, %2;"
                     :: "r"(dst), "l"(src), "r"(sz));
    }
}

// stage full 128x128 W tile (8 iterations of 256 threads)
__device__ __forceinline__ void stage_Wfull(const __half* __restrict__ W,
                                            uint32_t sdst, int tid, int ldW) {
    #pragma unroll
    for (int it = 0; it < 8; it++) {
        int idx = tid + it * 256;
        int r = idx >> 4, c8 = idx & 15;
        const __half* src = W + (size_t)r * ldW + c8 * 8;
        uint32_t dst = sdst + (r * TPAD + c8 * 8) * 2;
        asm volatile("cp.async.cg.shared.global [%0], [%1], 16, 16;"
                     :: "r"(dst), "l"(src));
    }
}

__device__ __forceinline__ void mma_half(const uint32_t* aAddr, const uint32_t* bAddr,
                                         int ks0, float acc[4][4][4]) {
    #pragma unroll
    for (int ks = ks0; ks < ks0 + 4; ks++) {
        uint32_t koff = (uint32_t)(ks * 32);
        uint32_t a[4][4], b[2][4];
        #pragma unroll
        for (int j2 = 0; j2 < 2; j2++)
            LDSM_X4(b[j2][0], b[j2][1], b[j2][2], b[j2][3], bAddr[j2] + koff);
        #pragma unroll
        for (int i = 0; i < 4; i++)
            LDSM_X4(a[i][0], a[i][1], a[i][2], a[i][3], aAddr[i] + koff);
        #pragma unroll
        for (int i = 0; i < 4; i++)
            #pragma unroll
            for (int j = 0; j < 4; j++) {
                const uint32_t* bf = &b[j >> 1][(j & 1) * 2];
                asm volatile(
                    "mma.sync.aligned.m16n8k16.row.col.f32.f16.f16.f32 "
                    "{%0,%1,%2,%3}, {%4,%5,%6,%7}, {%8,%9}, {%0,%1,%2,%3};"
                    : "+f"(acc[i][j][0]), "+f"(acc[i][j][1]),
                      "+f"(acc[i][j][2]), "+f"(acc[i][j][3])
                    : "r"(a[i][0]), "r"(a[i][1]), "r"(a[i][2]), "r"(a[i][3]),
                      "r"(bf[0]), "r"(bf[1]));
            }
    }
}

__device__ __forceinline__ void ldsm_bases(uint32_t sAs, uint32_t sWs, int lane,
                                           int wm, int wn, uint32_t* aAddr, uint32_t* bAddr) {
    int t7 = lane & 7, sel = lane >> 3;
    #pragma unroll
    for (int i = 0; i < 4; i++)
        aAddr[i] = sAs + 2 * ((wm * 64 + i * 16 + (sel & 1) * 8 + t7) * TPAD + (sel >> 1) * 8);
    #pragma unroll
    for (int j2 = 0; j2 < 2; j2++)
        bAddr[j2] = sWs + 2 * ((wn * 32 + j2 * 16 + (sel >> 1) * 8 + t7) * TPAD + (sel & 1) * 8);
}

// ---------------- fused h-GEMM: per-type M (fp16) + gh (fp16) --------------
__global__ void __launch_bounds__(256, 2)
fusedh_kernel(const __half* __restrict__ A,
              const __half* __restrict__ msgW, const __half* __restrict__ whh,
              const float* __restrict__ bhh,
              __half* __restrict__ Mout, __half* __restrict__ ghout, int ybase)
{
    extern __shared__ __half smem[];
    __half* As = smem;
    __half* Ws = smem + 128 * TPAD;

    const int tid  = threadIdx.x;
    const int lane = tid & 31, warp = tid >> 5;
    const int wm = warp & 1, wn = warp >> 1;
    const int g  = lane >> 2, t4 = lane & 3;
    const int row_base = blockIdx.x * 128;
    const int yy = blockIdx.y + ybase;
    const bool is_msg = (yy < TT);
    const int cb = is_msg ? 0 : (yy - TT) * 128;
    const __half* W = is_msg ? (msgW + (size_t)yy * HH * HH)
                             : (whh + (size_t)cb * HH);

    const uint32_t sAs = smem_u32(As);
    const uint32_t sWs = smem_u32(Ws);
    uint32_t aAddr[4], bAddr[2];
    ldsm_bases(sAs, sWs, lane, wm, wn, aAddr, bAddr);

    float acc[4][4][4];
    #pragma unroll
    for (int i = 0; i < 4; i++)
        #pragma unroll
        for (int j = 0; j < 4; j++)
            #pragma unroll
            for (int q = 0; q < 4; q++) acc[i][j][q] = 0.f;

    stage_half(A, row_base, NN, sAs, 0, tid, HH);
    stage_half(W, 0, 1 << 30, sWs, 0, tid, HH);
    asm volatile("cp.async.commit_group;");
    stage_half(A, row_base, NN, sAs, 1, tid, HH);
    stage_half(W, 0, 1 << 30, sWs, 1, tid, HH);
    asm volatile("cp.async.commit_group;");

    asm volatile("cp.async.wait_group 1;" ::: "memory");
    __syncthreads();
    mma_half(aAddr, bAddr, 0, acc);
    asm volatile("cp.async.wait_group 0;" ::: "memory");
    __syncthreads();
    mma_half(aAddr, bAddr, 4, acc);

    if (is_msg) {
        __half* C = Mout + (size_t)yy * NN * HH;
        #pragma unroll
        for (int i = 0; i < 4; i++) {
            int r0 = row_base + wm * 64 + i * 16 + g;
            #pragma unroll
            for (int j = 0; j < 4; j++) {
                int col = wn * 32 + j * 8 + 2 * t4;
                __half2 h0 = __floats2half2_rn(acc[i][j][0], acc[i][j][1]);
                __half2 h1 = __floats2half2_rn(acc[i][j][2], acc[i][j][3]);
                if (r0 < NN)
                    *(uint32_t*)(C + (size_t)r0 * HH + col) = *(uint32_t*)&h0;
                if (r0 + 8 < NN)
                    *(uint32_t*)(C + (size_t)(r0 + 8) * HH + col) = *(uint32_t*)&h1;
            }
        }
    } else {
        #pragma unroll
        for (int i = 0; i < 4; i++) {
            int r0 = row_base + wm * 64 + i * 16 + g;
            #pragma unroll
            for (int j = 0; j < 4; j++) {
                int col = cb + wn * 32 + j * 8 + 2 * t4;
                float b0 = bhh[col], b1 = bhh[col + 1];
                __half2 h0 = __floats2half2_rn(acc[i][j][0] + b0, acc[i][j][1] + b1);
                __half2 h1 = __floats2half2_rn(acc[i][j][2] + b0, acc[i][j][3] + b1);
                if (r0 < NN)
                    *(uint32_t*)(ghout + (size_t)r0 * G3H + col) = *(uint32_t*)&h0;
                if (r0 + 8 < NN)
                    *(uint32_t*)(ghout + (size_t)(r0 + 8) * G3H + col) = *(uint32_t*)&h1;
            }
        }
    }
}

// ---------------- generic Wih GEMM (used only for gxx precompute) ----------
__global__ void __launch_bounds__(256, 2)
tgemm16_kernel(const __half* __restrict__ A0,
               const __half* __restrict__ W, int ldW,
               const float* __restrict__ bias, __half* __restrict__ C)
{
    extern __shared__ __half smem[];
    __half* As = smem;
    __half* Ws = smem + 128 * TPAD;

    const int tid  = threadIdx.x;
    const int lane = tid & 31, warp = tid >> 5;
    const int wm = warp & 1, wn = warp >> 1;
    const int g  = lane >> 2, t4 = lane & 3;
    const int row_base = blockIdx.x * 128;
    const int cb = blockIdx.y * 128;

    const uint32_t sAs = smem_u32(As);
    const uint32_t sWs = smem_u32(Ws);
    uint32_t aAddr[4], bAddr[2];
    ldsm_bases(sAs, sWs, lane, wm, wn, aAddr, bAddr);

    float acc[4][4][4];
    #pragma unroll
    for (int i = 0; i < 4; i++)
        #pragma unroll
        for (int j = 0; j < 4; j++)
            #pragma unroll
            for (int q = 0; q < 4; q++) acc[i][j][q] = 0.f;

    const __half* Wc = W + (size_t)cb * ldW;
    stage_half(A0, row_base, NN, sAs, 0, tid, HH);
    stage_half(Wc, 0, 1 << 30, sWs, 0, tid, ldW);
    asm volatile("cp.async.commit_group;");
    stage_half(A0, row_base, NN, sAs, 1, tid, HH);
    stage_half(Wc, 0, 1 << 30, sWs, 1, tid, ldW);
    asm volatile("cp.async.commit_group;");

    asm volatile("cp.async.wait_group 1;" ::: "memory");
    __syncthreads();
    mma_half(aAddr, bAddr, 0, acc);
    asm volatile("cp.async.wait_group 0;" ::: "memory");
    __syncthreads();
    mma_half(aAddr, bAddr, 4, acc);

    #pragma unroll
    for (int i = 0; i < 4; i++) {
        int r0 = row_base + wm * 64 + i * 16 + g;
        #pragma unroll
        for (int j = 0; j < 4; j++) {
            int col = cb + wn * 32 + j * 8 + 2 * t4;
            float b0 = bias[col], b1 = bias[col + 1];
            __half2 h0 = __floats2half2_rn(acc[i][j][0] + b0, acc[i][j][1] + b1);
            __half2 h1 = __floats2half2_rn(acc[i][j][2] + b0, acc[i][j][3] + b1);
            if (r0 < NN)
                *(uint32_t*)(C + (size_t)r0 * G3H + col) = *(uint32_t*)&h0;
            if (r0 + 8 < NN)
                *(uint32_t*)(C + (size_t)(r0 + 8) * G3H + col) = *(uint32_t*)&h1;
        }
    }
}

// ---------------- fused gather + Wih GEMM --------------------------------
// CTA: 64 nodes. Phase 1: gather inc into A smem tile (fp16).
// Phase 2: loop 3 col-blocks, double-buffered W stage, gx out.
__global__ void __launch_bounds__(256, 2)
fusedgx_kernel(const __half* __restrict__ Wih, int ldW,
               const float* __restrict__ bias, const __half* __restrict__ addbase,
               const float* __restrict__ msgb, __half* __restrict__ gxout)
{
    extern __shared__ __half smem[];
    __half* As  = smem;                    // 64 x TPAD
    __half* Ws0 = smem + 64 * TPAD;        // 128 x TPAD
    __half* Ws1 = Ws0 + 128 * TPAD;        // 128 x TPAD
    float*  sb  = (float*)(Ws1 + 128 * TPAD);  // TT*HH floats

    const int tid  = threadIdx.x;
    const int lane = tid & 31, warp = tid >> 5;
    const int wm = warp & 1, wn = warp >> 1;
    const int g  = lane >> 2, t4 = lane & 3;
    const int row_base = blockIdx.x * 64;

    for (int i = tid; i < TT * HH; i += 256) sb[i] = msgb[i];
    __syncthreads();

    // ---- phase 1: gather (warp-per-node, 8 nodes per warp) ----
    #pragma unroll 1
    for (int k = 0; k < 8; k++) {
        int r = warp * 8 + k;
        int node = row_base + r;
        float4 acc = make_float4(0.f, 0.f, 0.f, 0.f);
        unsigned counts = 0;
        if (node < NN) {
            int s = g_off[node], e = g_off[node + 1];
            int i = s;
            for (; i + 4 <= e; i += 4) {
                unsigned e0 = g_ent[i], e1 = g_ent[i+1], e2 = g_ent[i+2], e3 = g_ent[i+3];
                uint2 m0 = *(const uint2*)(g_M16 + ((size_t)(e0 >> 16)*NN + (e0 & 0xFFFFu))*HH + lane*4);
                uint2 m1 = *(const uint2*)(g_M16 + ((size_t)(e1 >> 16)*NN + (e1 & 0xFFFFu))*HH + lane*4);
                uint2 m2 = *(const uint2*)(g_M16 + ((size_t)(e2 >> 16)*NN + (e2 & 0xFFFFu))*HH + lane*4);
                uint2 m3 = *(const uint2*)(g_M16 + ((size_t)(e3 >> 16)*NN + (e3 & 0xFFFFu))*HH + lane*4);
                counts += (1u << ((e0 >> 16) * 8)) + (1u << ((e1 >> 16) * 8))
                        + (1u << ((e2 >> 16) * 8)) + (1u << ((e3 >> 16) * 8));
                #pragma unroll
                for (int u = 0; u < 4; u++) {
                    uint2 mv = (u == 0) ? m0 : (u == 1) ? m1 : (u == 2) ? m2 : m3;
                    float2 a0 = __half22float2(*(__half2*)&mv.x);
                    float2 a1 = __half22float2(*(__half2*)&mv.y);
                    acc.x += a0.x; acc.y += a0.y; acc.z += a1.x; acc.w += a1.y;
                }
            }
            for (; i < e; i++) {
                unsigned ent = g_ent[i];
                uint2 mv = *(const uint2*)(g_M16 + ((size_t)(ent >> 16)*NN + (ent & 0xFFFFu))*HH + lane*4);
                counts += 1u << ((ent >> 16) * 8);
                float2 a0 = __half22float2(*(__half2*)&mv.x);
                float2 a1 = __half22float2(*(__half2*)&mv.y);
                acc.x += a0.x; acc.y += a0.y; acc.z += a1.x; acc.w += a1.y;
            }
            #pragma unroll
            for (int t = 0; t < TT; t++) {
                float c = (float)((counts >> (t * 8)) & 255u);
                const float* bp = sb + t * HH + lane * 4;
                acc.x += c * bp[0];
                acc.y += c * bp[1];
                acc.z += c * bp[2];
                acc.w += c * bp[3];
            }
        }
        __half2 p0 = __floats2half2_rn(acc.x, acc.y);
        __half2 p1 = __floats2half2_rn(acc.z, acc.w);
        uint2 pk = make_uint2(*(uint32_t*)&p0, *(uint32_t*)&p1);
        *(uint2*)((char*)As + r * (TPAD * 2) + lane * 8) = pk;
    }
    __syncthreads();

    // ---- phase 2: 3 col-blocks, double-buffered W ----
    const uint32_t sAs  = smem_u32(As);
    const uint32_t sWsB[2] = { smem_u32(Ws0), smem_u32(Ws1) };
    const int t7 = lane & 7, sel = lane >> 3;
    uint32_t aAddr[2];
    #pragma unroll
    for (int i = 0; i < 2; i++)
        aAddr[i] = sAs + 2 * ((wm * 32 + i * 16 + (sel & 1) * 8 + t7) * TPAD + (sel >> 1) * 8);

    stage_Wfull(Wih, sWsB[0], tid, ldW);
    asm volatile("cp.async.commit_group;");

    for (int b = 0; b < 3; b++) {
        if (b < 2) {
            stage_Wfull(Wih + (size_t)(b + 1) * 128 * ldW, sWsB[(b + 1) & 1], tid, ldW);
            asm volatile("cp.async.commit_group;");
        }
        if (b < 2) { asm volatile("cp.async.wait_group 1;" ::: "memory"); }
        else       { asm volatile("cp.async.wait_group 0;" ::: "memory"); }
        __syncthreads();

        uint32_t sW = sWsB[b & 1];
        uint32_t bAddr[2];
        #pragma unroll
        for (int j2 = 0; j2 < 2; j2++)
            bAddr[j2] = sW + 2 * ((wn * 32 + j2 * 16 + (sel >> 1) * 8 + t7) * TPAD + (sel & 1) * 8);

        float acc[2][4][4];
        #pragma unroll
        for (int i = 0; i < 2; i++)
            #pragma unroll
            for (int j = 0; j < 4; j++)
                #pragma unroll
                for (int q = 0; q < 4; q++) acc[i][j][q] = 0.f;

        #pragma unroll
        for (int ks = 0; ks < 8; ks++) {
            uint32_t koff = (uint32_t)(ks * 32);
            uint32_t a[2][4], bb[2][4];
            #pragma unroll
            for (int j2 = 0; j2 < 2; j2++)
                LDSM_X4(bb[j2][0], bb[j2][1], bb[j2][2], bb[j2][3], bAddr[j2] + koff);
            #pragma unroll
            for (int i = 0; i < 2; i++)
                LDSM_X4(a[i][0], a[i][1], a[i][2], a[i][3], aAddr[i] + koff);
            #pragma unroll
            for (int i = 0; i < 2; i++)
                #pragma unroll
                for (int j = 0; j < 4; j++) {
                    const uint32_t* bf = &bb[j >> 1][(j & 1) * 2];
                    asm volatile(
                        "mma.sync.aligned.m16n8k16.row.col.f32.f16.f16.f32 "
                        "{%0,%1,%2,%3}, {%4,%5,%6,%7}, {%8,%9}, {%0,%1,%2,%3};"
                        : "+f"(acc[i][j][0]), "+f"(acc[i][j][1]),
                          "+f"(acc[i][j][2]), "+f"(acc[i][j][3])
                        : "r"(a[i][0]), "r"(a[i][1]), "r"(a[i][2]), "r"(a[i][3]),
                          "r"(bf[0]), "r"(bf[1]));
                }
        }

        #pragma unroll
        for (int i = 0; i < 2; i++) {
            int r0 = row_base + wm * 32 + i * 16 + g;
            #pragma unroll
            for (int j = 0; j < 4; j++) {
                int col = b * 128 + wn * 32 + j * 8 + 2 * t4;
                float b0 = bias ? bias[col]     : 0.f;
                float b1 = bias ? bias[col + 1] : 0.f;
                float v0 = acc[i][j][0] + b0, v1 = acc[i][j][1] + b1;
                float v2 = acc[i][j][2] + b0, v3 = acc[i][j][3] + b1;
                if (addbase) {
                    if (r0 < NN) {
                        float2 ab = __half22float2(
                            *(const __half2*)(addbase + (size_t)r0 * G3H + col));
                        v0 += ab.x; v1 += ab.y;
                    }
                    if (r0 + 8 < NN) {
                        float2 ab = __half22float2(
                            *(const __half2*)(addbase + (size_t)(r0 + 8) * G3H + col));
                        v2 += ab.x; v3 += ab.y;
                    }
                }
                __half2 h0 = __floats2half2_rn(v0, v1);
                __half2 h1 = __floats2half2_rn(v2, v3);
                if (r0 < NN)
                    *(uint32_t*)(gxout + (size_t)r0 * G3H + col) = *(uint32_t*)&h0;
                if (r0 + 8 < NN)
                    *(uint32_t*)(gxout + (size_t)(r0 + 8) * G3H + col) = *(uint32_t*)&h1;
            }
        }
        __syncthreads();
    }
}

// ---------------- fused GRU gate: 4 features/thread ----------------
__global__ void gate_kernel(const float* __restrict__ h, float* __restrict__ hout) {
    int idx4 = blockIdx.x * blockDim.x + threadIdx.x;
    if (idx4 >= NN * 32) return;
    int n = idx4 >> 5, f4 = (idx4 & 31) * 4;
    const __half* gx = g_gx16 + (size_t)n * G3H + f4;
    const __half* gh = g_gh16 + (size_t)n * G3H + f4;
    uint2 uxr = *(const uint2*)gx;
    uint2 uxz = *(const uint2*)(gx + HH);
    uint2 uxn = *(const uint2*)(gx + 2 * HH);
    uint2 uhr = *(const uint2*)gh;
    uint2 uhz = *(const uint2*)(gh + HH);
    uint2 uhn = *(const uint2*)(gh + 2 * HH);
    float4 hv = *(const float4*)(h + (size_t)n * HH + f4);

    float o[4], hvv[4] = {hv.x, hv.y, hv.z, hv.w};
    #pragma unroll
    for (int u = 0; u < 2; u++) {
        float2 xr = __half22float2(*(__half2*)(&uxr.x + u));
        float2 xz = __half22float2(*(__half2*)(&uxz.x + u));
        float2 xn = __half22float2(*(__half2*)(&uxn.x + u));
        float2 hr = __half22float2(*(__half2*)(&uhr.x + u));
        float2 hz = __half22float2(*(__half2*)(&uhz.x + u));
        float2 hn = __half22float2(*(__half2*)(&uhn.x + u));
        float r0 = 1.f / (1.f + expf(-(xr.x + hr.x)));
        float r1 = 1.f / (1.f + expf(-(xr.y + hr.y)));
        float z0 = 1.f / (1.f + expf(-(xz.x + hz.x)));
        float z1 = 1.f / (1.f + expf(-(xz.y + hz.y)));
        float n0 = tanhf(xn.x + r0 * hn.x);
        float n1 = tanhf(xn.y + r1 * hn.y);
        o[2*u]   = (1.f - z0) * n0 + z0 * hvv[2*u];
        o[2*u+1] = (1.f - z1) * n1 + z1 * hvv[2*u+1];
    }

    *(float4*)(hout + (size_t)n * HH + f4) = make_float4(o[0], o[1], o[2], o[3]);
    __half2 oh0 = __floats2half2_rn(o[0], o[1]);
    __half2 oh1 = __floats2half2_rn(o[2], o[3]);
    uint2 pk = make_uint2(*(uint32_t*)&oh0, *(uint32_t*)&oh1);
    *(uint2*)(g_h16 + (size_t)n * HH + f4) = pk;
}

// ---------------- launch ----------------
extern "C" void kernel_launch(void* const* d_in, const int* in_sizes, int n_in,
                              void* d_out, int out_size) {
    const float* x      = (const float*)d_in[0];
    const int*   edges  = (const int*)  d_in[1];
    const float* msg_W  = (const float*)d_in[2];
    const float* msg_b  = (const float*)d_in[3];
    const float* g0_Wih = (const float*)d_in[4];
    const float* g0_Whh = (const float*)d_in[5];
    const float* g0_bih = (const float*)d_in[6];
    const float* g0_bhh = (const float*)d_in[7];
    const float* g1_Wih = (const float*)d_in[8];
    const float* g1_Whh = (const float*)d_in[9];
    const float* g1_bih = (const float*)d_in[10];
    const float* g1_bhh = (const float*)d_in[11];

    float *pH; int *pCnt;
    __half *pM16, *pH16, *pX16, *pW16, *pGx16, *pGh16, *pGxx16;
    cudaGetSymbolAddress((void**)&pM16,  g_M16);
    cudaGetSymbolAddress((void**)&pGx16, g_gx16);
    cudaGetSymbolAddress((void**)&pGh16, g_gh16);
    cudaGetSymbolAddress((void**)&pGxx16,g_gxx16);
    cudaGetSymbolAddress((void**)&pH,    g_h);
    cudaGetSymbolAddress((void**)&pCnt,  g_cnt);
    cudaGetSymbolAddress((void**)&pH16,  g_h16);
    cudaGetSymbolAddress((void**)&pX16,  g_x16);
    cudaGetSymbolAddress((void**)&pW16,  g_w16);

    const int SMEM   = 2 * 128 * TPAD * 2;                     // 69632 B
    const int SMEMGX = (64 + 256) * TPAD * 2 + TT * HH * 4;    // 89088 B
    cudaFuncSetAttribute(fusedh_kernel,
                         cudaFuncAttributeMaxDynamicSharedMemorySize, SMEM);
    cudaFuncSetAttribute(tgemm16_kernel,
                         cudaFuncAttributeMaxDynamicSharedMemorySize, SMEM);
    cudaFuncSetAttribute(fusedgx_kernel,
                         cudaFuncAttributeMaxDynamicSharedMemorySize, SMEMGX);

    static cudaStream_t s1 = nullptr;
    static cudaEvent_t evFork = nullptr, evGh = nullptr, evCsr = nullptr,
                       evConv = nullptr, evGxx = nullptr;
    if (s1 == nullptr) {
        cudaStreamCreateWithFlags(&s1, cudaStreamNonBlocking);
        cudaEventCreateWithFlags(&evFork, cudaEventDisableTiming);
        cudaEventCreateWithFlags(&evGh,   cudaEventDisableTiming);
        cudaEventCreateWithFlags(&evCsr,  cudaEventDisableTiming);
        cudaEventCreateWithFlags(&evConv, cudaEventDisableTiming);
        cudaEventCreateWithFlags(&evGxx,  cudaEventDisableTiming);
    }

    const int GX  = (NN + 127) / 128;   // 391
    const int GX2 = (NN + 63) / 64;     // 782

    // fork: CSR build on s1, prologue conversion on main
    cudaEventRecord(evFork, 0);
    cudaStreamWaitEvent(s1, evFork, 0);
    cudaMemsetAsync(pCnt, 0, NN * sizeof(int), s1);
    hist_kernel<<<(NE + 255) / 256, 256, 0, s1>>>(edges);
    scan_kernel<<<1, 1024, 0, s1>>>();
    fill_kernel<<<(NE + 255) / 256, 256, 0, s1>>>(edges);
    cudaEventRecord(evCsr, s1);

    {
        int total = NN * HH + 376832;
        conv_kernel<<<(total + 255) / 256, 256>>>(x, msg_W, g0_Wih, g0_Whh,
                                                  g1_Wih, g1_Whh);
    }
    cudaEventRecord(evConv, 0);
    // gxx = x @ W1ihA^T + g1_bih, off critical path (overlaps layer 0)
    cudaStreamWaitEvent(s1, evConv, 0);
    tgemm16_kernel<<<dim3(GX, 3), 256, SMEM, s1>>>(
        pX16, pW16 + OFF_W1IH, 2 * HH, g1_bih, pGxx16);
    cudaEventRecord(evGxx, s1);

    // CSR needed before first fusedgx
    cudaStreamWaitEvent(0, evCsr, 0);

    for (int l = 0; l < 2; l++) {
        const __half* whh = pW16 + (l ? OFF_W1HH : OFF_W0HH);
        const float*  bhh = l ? g1_bhh : g0_bhh;
        const __half* mw  = pW16 + OFF_MSGW + (size_t)l * TT * HH * HH;
        if (l == 1) cudaStreamWaitEvent(0, evGxx, 0);
        for (int s = 0; s < 3; s++) {
            fusedh_kernel<<<dim3(GX, TT), 256, SMEM>>>(
                pH16, mw, whh, bhh, pM16, pGh16, 0);
            cudaEventRecord(evFork, 0);
            cudaStreamWaitEvent(s1, evFork, 0);
            fusedh_kernel<<<dim3(GX, 3), 256, SMEM, s1>>>(
                pH16, mw, whh, bhh, pM16, pGh16, TT);
            cudaEventRecord(evGh, s1);
            // fused gather + Wih GEMM (concurrent with gh on s1)
            if (l == 0)
                fusedgx_kernel<<<GX2, 256, SMEMGX>>>(
                    pW16 + OFF_W0IH, HH, g0_bih, nullptr,
                    msg_b + (size_t)l * TT * HH, pGx16);
            else
                fusedgx_kernel<<<GX2, 256, SMEMGX>>>(
                    pW16 + OFF_W1IH + 128, 2 * HH, nullptr, pGxx16,
                    msg_b + (size_t)l * TT * HH, pGx16);
            cudaStreamWaitEvent(0, evGh, 0);
            bool last = (l == 1 && s == 2);
            gate_kernel<<<(NN * 32 + 255) / 256, 256>>>(pH, last ? (float*)d_out : pH);
        }
    }
}

// round 16
// speedup vs baseline: 1.2732x; 1.2732x over previous
#include <cuda_runtime.h>
#include <cuda_fp16.h>
#include <math.h>
#include <stdint.h>

#define NN 50000
#define HH 128
#define TT 4
#define EE 150000
#define NE (TT*EE)
#define G3H 384
#define TPAD 136   // halves per smem tile row

// ---------------- scratch (device globals; no allocation allowed) ----------
__device__ __half   g_M16[(size_t)TT*NN*HH];
__device__ __half   g_gx16[(size_t)NN*G3H];
__device__ __half   g_gh16[(size_t)NN*G3H];
__device__ __half   g_h16[(size_t)NN*HH];
__device__ __half   g_x16[(size_t)NN*HH];
__device__ __half   g_inc16[(size_t)NN*HH];
__device__ __half   g_w16[376832];
__device__ int      g_cnt[NN];
__device__ int      g_off[NN+1];
__device__ int      g_pos[NN];
__device__ unsigned g_ent[NE];

#define OFF_MSGW  0
#define OFF_W0IH  131072
#define OFF_W0HH  180224
#define OFF_W1IH  229376
#define OFF_W1HH  327680

__device__ __forceinline__ uint32_t smem_u32(const void* p) {
    uint32_t a;
    asm("{ .reg .u64 t; cvta.to.shared.u64 t, %1; cvt.u32.u64 %0, t; }" : "=r"(a) : "l"(p));
    return a;
}

#define LDSM_X4(r0, r1, r2, r3, addr) \
    asm volatile("ldmatrix.sync.aligned.m8n8.x4.shared.b16 {%0,%1,%2,%3}, [%4];" \
        : "=r"(r0), "=r"(r1), "=r"(r2), "=r"(r3) : "r"(addr))

// ---------------- fused prologue convert ----------------
__global__ void conv_kernel(const float* __restrict__ x,
                            const float* __restrict__ msgW,
                            const float* __restrict__ w0ih, const float* __restrict__ w0hh,
                            const float* __restrict__ w1ih, const float* __restrict__ w1hh)
{
    int i = blockIdx.x * blockDim.x + threadIdx.x;
    if (i < NN*HH) {
        __half hv = __float2half_rn(x[i]);
        g_h16[i] = hv;
        g_x16[i] = hv;
    } else {
        int j = i - NN*HH;
        if (j < 131072)       g_w16[OFF_MSGW + j]            = __float2half_rn(msgW[j]);
        else if (j < 180224)  g_w16[OFF_W0IH + (j - 131072)] = __float2half_rn(w0ih[j - 131072]);
        else if (j < 229376)  g_w16[OFF_W0HH + (j - 180224)] = __float2half_rn(w0hh[j - 180224]);
        else if (j < 327680)  g_w16[OFF_W1IH + (j - 229376)] = __float2half_rn(w1ih[j - 229376]);
        else if (j < 376832)  g_w16[OFF_W1HH + (j - 327680)] = __float2half_rn(w1hh[j - 327680]);
    }
}

// ---------------- CSR build ----------------
__global__ void hist_kernel(const int* __restrict__ edges) {
    int i = blockIdx.x * blockDim.x + threadIdx.x;
    if (i < NE) atomicAdd(&g_cnt[edges[2*i+1]], 1);
}

__global__ void scan_kernel() {
    __shared__ int s[1024];
    __shared__ int carry;
    if (threadIdx.x == 0) carry = 0;
    __syncthreads();
    for (int base = 0; base < NN; base += 1024) {
        int i = base + threadIdx.x;
        int v = (i < NN) ? g_cnt[i] : 0;
        s[threadIdx.x] = v;
        __syncthreads();
        #pragma unroll
        for (int off = 1; off < 1024; off <<= 1) {
            int t = (threadIdx.x >= off) ? s[threadIdx.x - off] : 0;
            __syncthreads();
            s[threadIdx.x] += t;
            __syncthreads();
        }
        int excl = carry + s[threadIdx.x] - v;
        if (i < NN) { g_off[i] = excl; g_pos[i] = excl; }
        __syncthreads();
        if (threadIdx.x == 1023) carry += s[1023];
        __syncthreads();
    }
    if (threadIdx.x == 0) g_off[NN] = carry;
}

__global__ void fill_kernel(const int* __restrict__ edges) {
    int i = blockIdx.x * blockDim.x + threadIdx.x;
    if (i < NE) {
        int t   = i / EE;
        int src = edges[2*i];
        int tgt = edges[2*i+1];
        int p = atomicAdd(&g_pos[tgt], 1);
        g_ent[p] = ((unsigned)t << 16) | (unsigned)src;
    }
}

// ---------------- message gather: unroll-4 for MLP ----------------
__global__ void gather_kernel(const float* __restrict__ b) {
    __shared__ float sb[TT*HH];
    for (int i = threadIdx.x; i < TT*HH; i += blockDim.x) sb[i] = b[i];
    __syncthreads();

    int gw   = (blockIdx.x * blockDim.x + threadIdx.x) >> 5;
    int lane = threadIdx.x & 31;
    if (gw >= NN) return;
    int s = g_off[gw], e = g_off[gw+1];
    float4 acc = make_float4(0.f, 0.f, 0.f, 0.f);

    int i = s;
    for (; i + 4 <= e; i += 4) {
        unsigned e0 = g_ent[i], e1 = g_ent[i+1], e2 = g_ent[i+2], e3 = g_ent[i+3];
        uint2 m0 = *(const uint2*)(g_M16 + ((size_t)(e0 >> 16)*NN + (e0 & 0xFFFFu))*HH + lane*4);
        uint2 m1 = *(const uint2*)(g_M16 + ((size_t)(e1 >> 16)*NN + (e1 & 0xFFFFu))*HH + lane*4);
        uint2 m2 = *(const uint2*)(g_M16 + ((size_t)(e2 >> 16)*NN + (e2 & 0xFFFFu))*HH + lane*4);
        uint2 m3 = *(const uint2*)(g_M16 + ((size_t)(e3 >> 16)*NN + (e3 & 0xFFFFu))*HH + lane*4);
        #pragma unroll
        for (int u = 0; u < 4; u++) {
            uint2 mv = (u == 0) ? m0 : (u == 1) ? m1 : (u == 2) ? m2 : m3;
            unsigned ent = (u == 0) ? e0 : (u == 1) ? e1 : (u == 2) ? e2 : e3;
            float2 a0 = __half22float2(*(__half2*)&mv.x);
            float2 a1 = __half22float2(*(__half2*)&mv.y);
            const float* bp = sb + (ent >> 16)*HH + lane*4;
            acc.x += a0.x + bp[0];
            acc.y += a0.y + bp[1];
            acc.z += a1.x + bp[2];
            acc.w += a1.y + bp[3];
        }
    }
    for (; i < e; i++) {
        unsigned ent = g_ent[i];
        uint2 mv = *(const uint2*)(g_M16 + ((size_t)(ent >> 16)*NN + (ent & 0xFFFFu))*HH + lane*4);
        float2 a0 = __half22float2(*(__half2*)&mv.x);
        float2 a1 = __half22float2(*(__half2*)&mv.y);
        const float* bp = sb + (ent >> 16)*HH + lane*4;
        acc.x += a0.x + bp[0];
        acc.y += a0.y + bp[1];
        acc.z += a1.x + bp[2];
        acc.w += a1.y + bp[3];
    }
    __half2 p0 = __floats2half2_rn(acc.x, acc.y);
    __half2 p1 = __floats2half2_rn(acc.z, acc.w);
    uint2 pk = make_uint2(*(uint32_t*)&p0, *(uint32_t*)&p1);
    *(uint2*)(g_inc16 + (size_t)gw*HH + lane*4) = pk;
}

// ======== shared GEMM mainloop pieces (ldmatrix + 2-stage K pipeline) ======
__device__ __forceinline__ void stage_half(const __half* __restrict__ A, int row_base,
                                           int row_limit, uint32_t sdst, int h, int tid,
                                           int ld) {
    #pragma unroll
    for (int it = 0; it < 4; it++) {
        int idx = tid + it * 256;
        int r = idx >> 3, c8 = (idx & 7) + h * 8;
        int gr = row_base + r;
        const __half* src = A + (size_t)(gr < row_limit ? gr : 0) * ld + c8 * 8;
        uint32_t dst = sdst + (r * TPAD + c8 * 8) * 2;
        int sz = (gr < row_limit) ? 16 : 0;
        asm volatile("cp.async.cg.shared.global [%0], [%1], 16, %2;"
                     :: "r"(dst), "l"(src), "r"(sz));
    }
}

__device__ __forceinline__ void mma_half(const uint32_t* aAddr, const uint32_t* bAddr,
                                         int ks0, float acc[4][4][4]) {
    #pragma unroll
    for (int ks = ks0; ks < ks0 + 4; ks++) {
        uint32_t koff = (uint32_t)(ks * 32);
        uint32_t a[4][4], b[2][4];
        #pragma unroll
        for (int j2 = 0; j2 < 2; j2++)
            LDSM_X4(b[j2][0], b[j2][1], b[j2][2], b[j2][3], bAddr[j2] + koff);
        #pragma unroll
        for (int i = 0; i < 4; i++)
            LDSM_X4(a[i][0], a[i][1], a[i][2], a[i][3], aAddr[i] + koff);
        #pragma unroll
        for (int i = 0; i < 4; i++)
            #pragma unroll
            for (int j = 0; j < 4; j++) {
                const uint32_t* bf = &b[j >> 1][(j & 1) * 2];
                asm volatile(
                    "mma.sync.aligned.m16n8k16.row.col.f32.f16.f16.f32 "
                    "{%0,%1,%2,%3}, {%4,%5,%6,%7}, {%8,%9}, {%0,%1,%2,%3};"
                    : "+f"(acc[i][j][0]), "+f"(acc[i][j][1]),
                      "+f"(acc[i][j][2]), "+f"(acc[i][j][3])
                    : "r"(a[i][0]), "r"(a[i][1]), "r"(a[i][2]), "r"(a[i][3]),
                      "r"(bf[0]), "r"(bf[1]));
            }
    }
}

__device__ __forceinline__ void ldsm_bases(uint32_t sAs, uint32_t sWs, int lane,
                                           int wm, int wn, uint32_t* aAddr, uint32_t* bAddr) {
    int t7 = lane & 7, sel = lane >> 3;
    #pragma unroll
    for (int i = 0; i < 4; i++)
        aAddr[i] = sAs + 2 * ((wm * 64 + i * 16 + (sel & 1) * 8 + t7) * TPAD + (sel >> 1) * 8);
    #pragma unroll
    for (int j2 = 0; j2 < 2; j2++)
        bAddr[j2] = sWs + 2 * ((wn * 32 + j2 * 16 + (sel >> 1) * 8 + t7) * TPAD + (sel & 1) * 8);
}

// ---------------- fused h-GEMM: per-type M (fp16) + gh (fp16) --------------
__global__ void __launch_bounds__(256, 2)
fusedh_kernel(const __half* __restrict__ A,
              const __half* __restrict__ msgW, const __half* __restrict__ whh,
              const float* __restrict__ bhh,
              __half* __restrict__ Mout, __half* __restrict__ ghout, int ybase)
{
    extern __shared__ __half smem[];
    __half* As = smem;
    __half* Ws = smem + 128 * TPAD;

    const int tid  = threadIdx.x;
    const int lane = tid & 31, warp = tid >> 5;
    const int wm = warp & 1, wn = warp >> 1;
    const int g  = lane >> 2, t4 = lane & 3;
    const int row_base = blockIdx.x * 128;
    const int yy = blockIdx.y + ybase;
    const bool is_msg = (yy < TT);
    const int cb = is_msg ? 0 : (yy - TT) * 128;
    const __half* W = is_msg ? (msgW + (size_t)yy * HH * HH)
                             : (whh + (size_t)cb * HH);

    const uint32_t sAs = smem_u32(As);
    const uint32_t sWs = smem_u32(Ws);
    uint32_t aAddr[4], bAddr[2];
    ldsm_bases(sAs, sWs, lane, wm, wn, aAddr, bAddr);

    float acc[4][4][4];
    #pragma unroll
    for (int i = 0; i < 4; i++)
        #pragma unroll
        for (int j = 0; j < 4; j++)
            #pragma unroll
            for (int q = 0; q < 4; q++) acc[i][j][q] = 0.f;

    stage_half(A, row_base, NN, sAs, 0, tid, HH);
    stage_half(W, 0, 1 << 30, sWs, 0, tid, HH);
    asm volatile("cp.async.commit_group;");
    stage_half(A, row_base, NN, sAs, 1, tid, HH);
    stage_half(W, 0, 1 << 30, sWs, 1, tid, HH);
    asm volatile("cp.async.commit_group;");

    asm volatile("cp.async.wait_group 1;" ::: "memory");
    __syncthreads();
    mma_half(aAddr, bAddr, 0, acc);
    asm volatile("cp.async.wait_group 0;" ::: "memory");
    __syncthreads();
    mma_half(aAddr, bAddr, 4, acc);

    if (is_msg) {
        __half* C = Mout + (size_t)yy * NN * HH;
        #pragma unroll
        for (int i = 0; i < 4; i++) {
            int r0 = row_base + wm * 64 + i * 16 + g;
            #pragma unroll
            for (int j = 0; j < 4; j++) {
                int col = wn * 32 + j * 8 + 2 * t4;
                __half2 h0 = __floats2half2_rn(acc[i][j][0], acc[i][j][1]);
                __half2 h1 = __floats2half2_rn(acc[i][j][2], acc[i][j][3]);
                if (r0 < NN)
                    *(uint32_t*)(C + (size_t)r0 * HH + col) = *(uint32_t*)&h0;
                if (r0 + 8 < NN)
                    *(uint32_t*)(C + (size_t)(r0 + 8) * HH + col) = *(uint32_t*)&h1;
            }
        }
    } else {
        #pragma unroll
        for (int i = 0; i < 4; i++) {
            int r0 = row_base + wm * 64 + i * 16 + g;
            #pragma unroll
            for (int j = 0; j < 4; j++) {
                int col = cb + wn * 32 + j * 8 + 2 * t4;
                float b0 = bhh[col], b1 = bhh[col + 1];
                __half2 h0 = __floats2half2_rn(acc[i][j][0] + b0, acc[i][j][1] + b1);
                __half2 h1 = __floats2half2_rn(acc[i][j][2] + b0, acc[i][j][3] + b1);
                if (r0 < NN)
                    *(uint32_t*)(ghout + (size_t)r0 * G3H + col) = *(uint32_t*)&h0;
                if (r0 + 8 < NN)
                    *(uint32_t*)(ghout + (size_t)(r0 + 8) * G3H + col) = *(uint32_t*)&h1;
            }
        }
    }
}

// ---------------- Wih GEMM: gx = [A0|A1] @ Wih^T + bih (fp16 out) ----------
__global__ void __launch_bounds__(256, 2)
tgemm16_kernel(const __half* __restrict__ A0, const __half* __restrict__ A1,
               const __half* __restrict__ W, int ldW,
               const float* __restrict__ bias, __half* __restrict__ C)
{
    extern __shared__ __half smem[];
    __half* As = smem;
    __half* Ws = smem + 128 * TPAD;

    const int tid  = threadIdx.x;
    const int lane = tid & 31, warp = tid >> 5;
    const int wm = warp & 1, wn = warp >> 1;
    const int g  = lane >> 2, t4 = lane & 3;
    const int row_base = blockIdx.x * 128;
    const int cb = blockIdx.y * 128;

    const uint32_t sAs = smem_u32(As);
    const uint32_t sWs = smem_u32(Ws);
    uint32_t aAddr[4], bAddr[2];
    ldsm_bases(sAs, sWs, lane, wm, wn, aAddr, bAddr);

    float acc[4][4][4];
    #pragma unroll
    for (int i = 0; i < 4; i++)
        #pragma unroll
        for (int j = 0; j < 4; j++)
            #pragma unroll
            for (int q = 0; q < 4; q++) acc[i][j][q] = 0.f;

    const int nch = (A1 != nullptr) ? 2 : 1;
    for (int ch = 0; ch < nch; ch++) {
        const __half* A = ch ? A1 : A0;
        const __half* Wc = W + (size_t)cb * ldW + ch * 128;
        stage_half(A, row_base, NN, sAs, 0, tid, HH);
        stage_half(Wc, 0, 1 << 30, sWs, 0, tid, ldW);
        asm volatile("cp.async.commit_group;");
        stage_half(A, row_base, NN, sAs, 1, tid, HH);
        stage_half(Wc, 0, 1 << 30, sWs, 1, tid, ldW);
        asm volatile("cp.async.commit_group;");

        asm volatile("cp.async.wait_group 1;" ::: "memory");
        __syncthreads();
        mma_half(aAddr, bAddr, 0, acc);
        asm volatile("cp.async.wait_group 0;" ::: "memory");
        __syncthreads();
        mma_half(aAddr, bAddr, 4, acc);
        if (ch + 1 < nch) __syncthreads();
    }

    #pragma unroll
    for (int i = 0; i < 4; i++) {
        int r0 = row_base + wm * 64 + i * 16 + g;
        #pragma unroll
        for (int j = 0; j < 4; j++) {
            int col = cb + wn * 32 + j * 8 + 2 * t4;
            float b0 = bias[col], b1 = bias[col + 1];
            __half2 h0 = __floats2half2_rn(acc[i][j][0] + b0, acc[i][j][1] + b1);
            __half2 h1 = __floats2half2_rn(acc[i][j][2] + b0, acc[i][j][3] + b1);
            if (r0 < NN)
                *(uint32_t*)(C + (size_t)r0 * G3H + col) = *(uint32_t*)&h0;
            if (r0 + 8 < NN)
                *(uint32_t*)(C + (size_t)(r0 + 8) * G3H + col) = *(uint32_t*)&h1;
        }
    }
}

// ---------------- fused GRU gate: fp16 state, 4 features/thread ------------
__global__ void gate_kernel(float* __restrict__ out, int last) {
    int idx4 = blockIdx.x * blockDim.x + threadIdx.x;
    if (idx4 >= NN * 32) return;
    int n = idx4 >> 5, f4 = (idx4 & 31) * 4;
    const __half* gx = g_gx16 + (size_t)n * G3H + f4;
    const __half* gh = g_gh16 + (size_t)n * G3H + f4;
    uint2 uxr = *(const uint2*)gx;
    uint2 uxz = *(const uint2*)(gx + HH);
    uint2 uxn = *(const uint2*)(gx + 2 * HH);
    uint2 uhr = *(const uint2*)gh;
    uint2 uhz = *(const uint2*)(gh + HH);
    uint2 uhn = *(const uint2*)(gh + 2 * HH);
    uint2 uh  = *(const uint2*)(g_h16 + (size_t)n * HH + f4);

    float o[4];
    #pragma unroll
    for (int u = 0; u < 2; u++) {
        float2 xr = __half22float2(*(__half2*)(&uxr.x + u));
        float2 xz = __half22float2(*(__half2*)(&uxz.x + u));
        float2 xn = __half22float2(*(__half2*)(&uxn.x + u));
        float2 hr = __half22float2(*(__half2*)(&uhr.x + u));
        float2 hz = __half22float2(*(__half2*)(&uhz.x + u));
        float2 hn = __half22float2(*(__half2*)(&uhn.x + u));
        float2 hv = __half22float2(*(__half2*)(&uh.x + u));
        float r0 = 1.f / (1.f + expf(-(xr.x + hr.x)));
        float r1 = 1.f / (1.f + expf(-(xr.y + hr.y)));
        float z0 = 1.f / (1.f + expf(-(xz.x + hz.x)));
        float z1 = 1.f / (1.f + expf(-(xz.y + hz.y)));
        float n0 = tanhf(xn.x + r0 * hn.x);
        float n1 = tanhf(xn.y + r1 * hn.y);
        o[2*u]   = (1.f - z0) * n0 + z0 * hv.x;
        o[2*u+1] = (1.f - z1) * n1 + z1 * hv.y;
    }

    __half2 oh0 = __floats2half2_rn(o[0], o[1]);
    __half2 oh1 = __floats2half2_rn(o[2], o[3]);
    uint2 pk = make_uint2(*(uint32_t*)&oh0, *(uint32_t*)&oh1);
    *(uint2*)(g_h16 + (size_t)n * HH + f4) = pk;
    if (last)
        *(float4*)(out + (size_t)n * HH + f4) = make_float4(o[0], o[1], o[2], o[3]);
}

// ---------------- launch ----------------
extern "C" void kernel_launch(void* const* d_in, const int* in_sizes, int n_in,
                              void* d_out, int out_size) {
    const float* x      = (const float*)d_in[0];
    const int*   edges  = (const int*)  d_in[1];
    const float* msg_W  = (const float*)d_in[2];
    const float* msg_b  = (const float*)d_in[3];
    const float* g0_Wih = (const float*)d_in[4];
    const float* g0_Whh = (const float*)d_in[5];
    const float* g0_bih = (const float*)d_in[6];
    const float* g0_bhh = (const float*)d_in[7];
    const float* g1_Wih = (const float*)d_in[8];
    const float* g1_Whh = (const float*)d_in[9];
    const float* g1_bih = (const float*)d_in[10];
    const float* g1_bhh = (const float*)d_in[11];

    int *pCnt;
    __half *pM16, *pH16, *pX16, *pInc16, *pW16, *pGx16, *pGh16;
    cudaGetSymbolAddress((void**)&pM16,  g_M16);
    cudaGetSymbolAddress((void**)&pGx16, g_gx16);
    cudaGetSymbolAddress((void**)&pGh16, g_gh16);
    cudaGetSymbolAddress((void**)&pCnt,  g_cnt);
    cudaGetSymbolAddress((void**)&pH16,  g_h16);
    cudaGetSymbolAddress((void**)&pX16,  g_x16);
    cudaGetSymbolAddress((void**)&pInc16,g_inc16);
    cudaGetSymbolAddress((void**)&pW16,  g_w16);

    const int SMEM = 2 * 128 * TPAD * 2;   // 69632 B
    cudaFuncSetAttribute(fusedh_kernel,
                         cudaFuncAttributeMaxDynamicSharedMemorySize, SMEM);
    cudaFuncSetAttribute(tgemm16_kernel,
                         cudaFuncAttributeMaxDynamicSharedMemorySize, SMEM);

    static cudaStream_t s1 = nullptr;
    static cudaEvent_t evFork = nullptr, evGh = nullptr, evCsr = nullptr;
    if (s1 == nullptr) {
        cudaStreamCreateWithFlags(&s1, cudaStreamNonBlocking);
        cudaEventCreateWithFlags(&evFork, cudaEventDisableTiming);
        cudaEventCreateWithFlags(&evGh,   cudaEventDisableTiming);
        cudaEventCreateWithFlags(&evCsr,  cudaEventDisableTiming);
    }

    cudaEventRecord(evFork, 0);
    cudaStreamWaitEvent(s1, evFork, 0);
    cudaMemsetAsync(pCnt, 0, NN * sizeof(int), s1);
    hist_kernel<<<(NE + 255) / 256, 256, 0, s1>>>(edges);
    scan_kernel<<<1, 1024, 0, s1>>>();
    fill_kernel<<<(NE + 255) / 256, 256, 0, s1>>>(edges);
    cudaEventRecord(evCsr, s1);

    {
        int total = NN * HH + 376832;
        conv_kernel<<<(total + 255) / 256, 256>>>(x, msg_W, g0_Wih, g0_Whh,
                                                  g1_Wih, g1_Whh);
    }
    cudaStreamWaitEvent(0, evCsr, 0);

    const int GX = (NN + 127) / 128;   // 391
    for (int l = 0; l < 2; l++) {
        const __half* whh = pW16 + (l ? OFF_W1HH : OFF_W0HH);
        const float*  bhh = l ? g1_bhh : g0_bhh;
        const float*  bih = l ? g1_bih : g0_bih;
        const __half* mw  = pW16 + OFF_MSGW + (size_t)l * TT * HH * HH;
        for (int s = 0; s < 3; s++) {
            fusedh_kernel<<<dim3(GX, TT), 256, SMEM>>>(
                pH16, mw, whh, bhh, pM16, pGh16, 0);
            cudaEventRecord(evFork, 0);
            cudaStreamWaitEvent(s1, evFork, 0);
            fusedh_kernel<<<dim3(GX, 3), 256, SMEM, s1>>>(
                pH16, mw, whh, bhh, pM16, pGh16, TT);
            cudaEventRecord(evGh, s1);
            gather_kernel<<<(NN * 32) / 256, 256>>>(msg_b + (size_t)l * TT * HH);
            if (l == 0)
                tgemm16_kernel<<<dim3(GX, 3), 256, SMEM>>>(
                    pInc16, nullptr, pW16 + OFF_W0IH, HH, bih, pGx16);
            else
                tgemm16_kernel<<<dim3(GX, 3), 256, SMEM>>>(
                    pX16, pInc16, pW16 + OFF_W1IH, 2 * HH, bih, pGx16);
            cudaStreamWaitEvent(0, evGh, 0);
            int last = (l == 1 && s == 2) ? 1 : 0;
            gate_kernel<<<(NN * 32 + 255) / 256, 256>>>((float*)d_out, last);
        }
    }
}